// round 2
// baseline (speedup 1.0000x reference)
#include <cuda_runtime.h>
#include <math.h>

// Problem constants
#define BATCH 8
#define HW 56
#define NPIX (HW*HW)        // 3136
#define CIN 64
#define COUT 64
#define CMID 32
#define CXV 512             // cout*8
#define CU 256              // cmid*8
#define KIN 512             // GEMM K (cin*8)
#define MROWS 768           // 512 xv rows + 256 u rows

// Scratch (device globals; no allocation allowed)
__device__ float g_W[MROWS * KIN];                 // expanded weights, row-major [m][k]
__device__ float g_xv[(size_t)BATCH * CXV * NPIX]; // value branch
__device__ float g_u[(size_t)BATCH * CU * NPIX];   // pre-GN dyn branch
__device__ float g_mean[BATCH * CMID];
__device__ float g_rstd[BATCH * CMID];

__constant__ int c_perm[8][8] = {
    {0, 1, 2, 3, 4, 5, 6, 7},
    {3, 0, 1, 2, 5, 6, 7, 4},
    {2, 3, 0, 1, 6, 7, 4, 5},
    {1, 2, 3, 0, 7, 4, 5, 6},
    {4, 5, 6, 7, 0, 1, 2, 3},
    {5, 6, 7, 4, 3, 0, 1, 2},
    {6, 7, 4, 5, 2, 3, 0, 1},
    {7, 4, 5, 6, 1, 2, 3, 0},
};

// source tap index (into wgt's 9 taps) for output tap t, per group element f
__constant__ int c_tap[8][9] = {
    {0,1,2,3,4,5,6,7,8},
    {2,5,8,1,4,7,0,3,6},
    {8,7,6,5,4,3,2,1,0},
    {6,3,0,7,4,1,8,5,2},
    {2,1,0,5,4,3,8,7,6},
    {8,5,2,7,4,1,6,3,0},
    {6,7,8,3,4,5,0,1,2},
    {0,3,6,1,4,7,2,5,8},
};

// ---------------------------------------------------------------------------
// Kernel 0: expand base weights into full 768x512 GEMM matrix
// rows 0..511: xv weights (o*8+g), rows 512..767: u weights
// ---------------------------------------------------------------------------
__global__ void expand_w_kernel(const float* __restrict__ w_v,
                                const float* __restrict__ w1) {
    int idx = blockIdx.x * 256 + threadIdx.x;
    if (idx >= MROWS * KIN) return;
    int m = idx / KIN, kk = idx - m * KIN;
    int i = kk >> 3, f = kk & 7;
    float val;
    if (m < 512) {
        int o = m >> 3, g = m & 7;
        val = w_v[(o * 64 + i) * 8 + c_perm[g][f]];
    } else {
        int m2 = m - 512;
        int o = m2 >> 3, g = m2 & 7;
        val = w1[(o * 64 + i) * 8 + c_perm[g][f]];
    }
    g_W[idx] = val;
}

// ---------------------------------------------------------------------------
// Kernel 1: SGEMM  C[768 x 3136] = W[768 x 512] * x_b[512 x 3136], per batch
// Block tile: 128(M) x 64(N), BK=16, 256 threads, 8x4 per-thread microtile
// ---------------------------------------------------------------------------
__global__ __launch_bounds__(256) void gemm_kernel(const float* __restrict__ x) {
    const int bn = blockIdx.x;    // 0..48
    const int bm = blockIdx.y;    // 0..5
    const int bb = blockIdx.z;    // batch

    __shared__ float As[16][132]; // [k][m], padded
    __shared__ float Bs[16][68];  // [k][n], padded

    const int tid = threadIdx.x;
    const int tx = tid & 15;      // N dir
    const int ty = tid >> 4;      // M dir

    const float* __restrict__ Bbase = x + (size_t)bb * KIN * NPIX + bn * 64;
    const float* __restrict__ Abase = g_W + (size_t)bm * 128 * KIN;

    const int a_m = tid >> 2;          // 0..63
    const int a_k = (tid & 3) * 4;     // 0,4,8,12
    const int b_n = tid & 63;
    const int b_k = tid >> 6;          // 0..3

    float acc[8][4];
#pragma unroll
    for (int r = 0; r < 8; r++)
#pragma unroll
        for (int c = 0; c < 4; c++) acc[r][c] = 0.f;

    for (int k0 = 0; k0 < KIN; k0 += 16) {
        float4 a0 = *(const float4*)(Abase + (size_t)a_m * KIN + k0 + a_k);
        float4 a1 = *(const float4*)(Abase + (size_t)(a_m + 64) * KIN + k0 + a_k);
        float b0 = Bbase[(size_t)(k0 + b_k) * NPIX + b_n];
        float b1 = Bbase[(size_t)(k0 + b_k + 4) * NPIX + b_n];
        float b2 = Bbase[(size_t)(k0 + b_k + 8) * NPIX + b_n];
        float b3 = Bbase[(size_t)(k0 + b_k + 12) * NPIX + b_n];

        __syncthreads();
        As[a_k + 0][a_m] = a0.x;  As[a_k + 1][a_m] = a0.y;
        As[a_k + 2][a_m] = a0.z;  As[a_k + 3][a_m] = a0.w;
        As[a_k + 0][a_m + 64] = a1.x;  As[a_k + 1][a_m + 64] = a1.y;
        As[a_k + 2][a_m + 64] = a1.z;  As[a_k + 3][a_m + 64] = a1.w;
        Bs[b_k][b_n] = b0;
        Bs[b_k + 4][b_n] = b1;
        Bs[b_k + 8][b_n] = b2;
        Bs[b_k + 12][b_n] = b3;
        __syncthreads();

#pragma unroll
        for (int k = 0; k < 16; k++) {
            float4 av0 = *(const float4*)&As[k][ty * 8];
            float4 av1 = *(const float4*)&As[k][ty * 8 + 4];
            float4 bv  = *(const float4*)&Bs[k][tx * 4];
            float am[8] = {av0.x, av0.y, av0.z, av0.w, av1.x, av1.y, av1.z, av1.w};
            float bm_[4] = {bv.x, bv.y, bv.z, bv.w};
#pragma unroll
            for (int r = 0; r < 8; r++)
#pragma unroll
                for (int c = 0; c < 4; c++) acc[r][c] = fmaf(am[r], bm_[c], acc[r][c]);
        }
    }

    // write out: rows bm*128 + ty*8 + r, cols bn*64 + tx*4 + c
    const int n_global = bn * 64 + tx * 4;
#pragma unroll
    for (int r = 0; r < 8; r++) {
        int m_global = bm * 128 + ty * 8 + r;
        float4 v = make_float4(acc[r][0], acc[r][1], acc[r][2], acc[r][3]);
        if (m_global < 512) {
            *(float4*)&g_xv[((size_t)bb * CXV + m_global) * NPIX + n_global] = v;
        } else {
            *(float4*)&g_u[((size_t)bb * CU + (m_global - 512)) * NPIX + n_global] = v;
        }
    }
}

// ---------------------------------------------------------------------------
// Kernel 2: GroupNorm stats. One block per (b, i) pair; reduce over 8*3136 vals
// ---------------------------------------------------------------------------
__global__ __launch_bounds__(256) void stats_kernel() {
    const int bi = blockIdx.x;        // b*32 + i
    const int b = bi >> 5, i = bi & 31;
    const float* __restrict__ base = g_u + ((size_t)b * CU + i * 8) * NPIX;
    const int n = 8 * NPIX;           // 25088

    float s = 0.f, s2 = 0.f;
    for (int idx = threadIdx.x; idx < n; idx += 256) {
        float v = base[idx];
        s += v;
        s2 += v * v;
    }
    __shared__ float ss[256], ss2[256];
    ss[threadIdx.x] = s;
    ss2[threadIdx.x] = s2;
    __syncthreads();
    for (int stride = 128; stride > 0; stride >>= 1) {
        if (threadIdx.x < stride) {
            ss[threadIdx.x] += ss[threadIdx.x + stride];
            ss2[threadIdx.x] += ss2[threadIdx.x + stride];
        }
        __syncthreads();
    }
    if (threadIdx.x == 0) {
        float mean = ss[0] / (float)n;
        float var = ss2[0] / (float)n - mean * mean;
        g_mean[bi] = mean;
        g_rstd[bi] = rsqrtf(var + 1e-5f);
    }
}

// ---------------------------------------------------------------------------
// Kernel 3: epilogue. One block = (b, f, G, 14x14 spatial tile).
// Phase A: per-pixel theta[9] = w2[G] @ relu(GN(u[:, f-slice])) + b2[G]
// Phase B: out[c] = sum_t theta[tapmap[f][t]] * xv[c, p + dt], c = 0..15
// ---------------------------------------------------------------------------
__global__ __launch_bounds__(256) void epi_kernel(const float* __restrict__ gn_gamma,
                                                  const float* __restrict__ gn_beta,
                                                  const float* __restrict__ w2,
                                                  const float* __restrict__ b2,
                                                  float* __restrict__ out) {
    const int tile = blockIdx.x;          // 0..15
    const int gf = blockIdx.y;            // f*4 + G
    const int bb = blockIdx.z;
    const int f = gf >> 2, G = gf & 3;
    const int ty0 = (tile >> 2) * 14;
    const int tx0 = (tile & 3) * 14;
    const int tid = threadIdx.x;

    __shared__ float xs[16][16][17];      // [c][yy][xx], padded
    __shared__ float th[9][200];          // theta by SOURCE tap, per pixel (196)
    __shared__ float s_w2[9][32];
    __shared__ float s_b2[9];
    __shared__ float s_gn[32][4];         // mean, rstd, gamma, beta per i

    // FIX(R1): 288 entries > 256 threads -> must loop (tap row 8 was garbage)
    for (int idx = tid; idx < 9 * 32; idx += 256) {
        int t = idx >> 5, i = idx & 31;
        s_w2[t][i] = w2[(G * 9 + t) * 32 + i];
    }
    if (tid < 9) s_b2[tid] = b2[G * 9 + tid];
    if (tid >= 32 && tid < 64) {
        int i = tid - 32;
        s_gn[i][0] = g_mean[bb * 32 + i];
        s_gn[i][1] = g_rstd[bb * 32 + i];
        s_gn[i][2] = gn_gamma[i * 8 + f];
        s_gn[i][3] = gn_beta[i * 8 + f];
    }

    // load padded xv tile (16 channels x 16x16)
    {
        int yy = tid >> 4, xx = tid & 15;
        int gy = ty0 - 1 + yy, gx = tx0 - 1 + xx;
        bool ok = (gy >= 0 && gy < HW && gx >= 0 && gx < HW);
        size_t base = ((size_t)bb * CXV + G * 128 + f) * NPIX + gy * HW + gx;
#pragma unroll
        for (int c = 0; c < 16; c++) {
            float v = 0.f;
            if (ok) v = g_xv[base + (size_t)c * 8 * NPIX];
            xs[c][yy][xx] = v;
        }
    }
    __syncthreads();

    if (tid < 196) {
        int py = tid / 14, px = tid - py * 14;
        int p = (ty0 + py) * HW + (tx0 + px);
        float acc[9];
#pragma unroll
        for (int t = 0; t < 9; t++) acc[t] = s_b2[t];
        const float* __restrict__ ub = g_u + ((size_t)bb * CU + f) * NPIX + p;
#pragma unroll 8
        for (int i = 0; i < 32; i++) {
            float v = ub[(size_t)i * 8 * NPIX];
            v = (v - s_gn[i][0]) * s_gn[i][1] * s_gn[i][2] + s_gn[i][3];
            v = fmaxf(v, 0.f);
#pragma unroll
            for (int t = 0; t < 9; t++) acc[t] = fmaf(s_w2[t][i], v, acc[t]);
        }
#pragma unroll
        for (int t = 0; t < 9; t++) th[t][tid] = acc[t];
    }
    __syncthreads();

    int tap[9];
#pragma unroll
    for (int t = 0; t < 9; t++) tap[t] = c_tap[f][t];

    for (int idx = tid; idx < 16 * 196; idx += 256) {
        int c = idx / 196, pix = idx - c * 196;
        int py = pix / 14, px = pix - py * 14;
        float acc = 0.f;
#pragma unroll
        for (int ti = 0; ti < 3; ti++)
#pragma unroll
            for (int tj = 0; tj < 3; tj++) {
                int t = ti * 3 + tj;
                acc = fmaf(th[tap[t]][pix], xs[c][py + ti][px + tj], acc);
            }
        int cfull = G * 128 + c * 8 + f;
        out[((size_t)bb * CXV + cfull) * NPIX + (ty0 + py) * HW + (tx0 + px)] = acc;
    }
}

// ---------------------------------------------------------------------------
extern "C" void kernel_launch(void* const* d_in, const int* in_sizes, int n_in,
                              void* d_out, int out_size) {
    const float* x        = (const float*)d_in[0];
    const float* w_v      = (const float*)d_in[1];
    const float* w1       = (const float*)d_in[2];
    const float* gn_gamma = (const float*)d_in[3];
    const float* gn_beta  = (const float*)d_in[4];
    const float* w2       = (const float*)d_in[5];
    const float* b2       = (const float*)d_in[6];
    float* out = (float*)d_out;

    expand_w_kernel<<<(MROWS * KIN + 255) / 256, 256>>>(w_v, w1);
    {
        dim3 grid(NPIX / 64, MROWS / 128, BATCH);   // (49, 6, 8)
        gemm_kernel<<<grid, 256>>>(x);
    }
    stats_kernel<<<BATCH * CMID, 256>>>();
    {
        dim3 grid(16, 32, BATCH);                   // (tiles, f*4+G, b)
        epi_kernel<<<grid, 256>>>(gn_gamma, gn_beta, w2, b2, out);
    }
}